// round 16
// baseline (speedup 1.0000x reference)
#include <cuda_runtime.h>
#include <cstdint>
#include <cstddef>

#define MD   28
#define D    784
#define SEQ  128
#define NB   512
#define NPC  5            // pieces per batch
#define PLEN 26           // steps per piece (5*26=130 >= 128; pad = identity row 0)
#define NWB  3            // warps per block
#define NBLK 444          // 3 blocks per SM exactly
#define NSEG (NB * NPC)   // 2560 segments; warp gw handles segs 2gw, 2gw+1
#define MAT_BYTES 3136
#define W_STRIDE  (4 * MAT_BYTES + 16)
#define SMEM_BYTES (NWB * W_STRIDE)

__device__ __align__(16) float g_q[(size_t)NSEG * D];   // piece partials
__device__ int g_cnt[NB];                               // fan-in counters

// ---------- packed f32x2 helpers ----------
__device__ __forceinline__ unsigned long long pack2(float lo, float hi) {
    unsigned long long r;
    asm("mov.b64 %0, {%1, %2};" : "=l"(r) : "f"(lo), "f"(hi));
    return r;
}
__device__ __forceinline__ void unpack2(unsigned long long v, float& lo, float& hi) {
    asm("mov.b64 {%0, %1}, %2;" : "=f"(lo), "=f"(hi) : "l"(v));
}
__device__ __forceinline__ unsigned long long mul2(unsigned long long a, unsigned long long b) {
    unsigned long long r;
    asm("mul.rn.f32x2 %0, %1, %2;" : "=l"(r) : "l"(a), "l"(b));
    return r;
}
__device__ __forceinline__ void fma2(unsigned long long& d, unsigned long long a, unsigned long long b) {
    asm("fma.rn.f32x2 %0, %1, %2, %0;" : "+l"(d) : "l"(a), "l"(b));
}

// ---------- TMA bulk-copy + mbarrier helpers ----------
__device__ __forceinline__ unsigned s2u(const void* p) {
    return (unsigned)__cvta_generic_to_shared(p);
}
__device__ __forceinline__ void mbar_init(void* mbar) {
    asm volatile("mbarrier.init.shared.b64 [%0], %1;"
                 :: "r"(s2u(mbar)), "r"(1u) : "memory");
}
__device__ __forceinline__ void mbar_expect_tx(void* mbar, unsigned bytes) {
    asm volatile("mbarrier.arrive.expect_tx.shared.b64 _, [%0], %1;"
                 :: "r"(s2u(mbar)), "r"(bytes) : "memory");
}
__device__ __forceinline__ void mbar_wait(void* mbar, unsigned parity) {
    asm volatile(
        "{\n\t"
        ".reg .pred P;\n"
        "W%=:\n\t"
        "mbarrier.try_wait.parity.acquire.cta.shared::cta.b64 P, [%0], %1, 0x989680;\n\t"
        "@P bra D%=;\n\t"
        "bra W%=;\n"
        "D%=:\n\t"
        "}"
        :: "r"(s2u(mbar)), "r"(parity) : "memory");
}
__device__ __forceinline__ void bulk_cp(void* dst_smem, const void* src_gmem,
                                        unsigned bytes, void* mbar) {
    asm volatile(
        "cp.async.bulk.shared::cta.global.mbarrier::complete_tx::bytes [%0], [%1], %2, [%3];"
        :: "r"(s2u(dst_smem)), "l"(src_gmem), "r"(bytes), "r"(s2u(mbar)) : "memory");
}
__device__ __forceinline__ void fence_proxy_async_cta() {
    asm volatile("fence.proxy.async.shared::cta;" ::: "memory");
}

// Two rows per lane: {c0,c1} = rows sl, sl+14. W in smem; the two 16-lane
// halves may pass different pointers (dual broadcast).
__device__ __forceinline__ void mm_step2(float c0[MD], float c1[MD],
                                         const float4* __restrict__ w) {
    unsigned long long a0[14], a1[14];
    #pragma unroll
    for (int k = 0; k < MD; ++k) {
        unsigned long long k0 = pack2(c0[k], c0[k]);
        unsigned long long k1 = pack2(c1[k], c1[k]);
        #pragma unroll
        for (int q = 0; q < 7; ++q) {
            float4 wv = w[k * 7 + q];
            unsigned long long wlo = pack2(wv.x, wv.y);
            unsigned long long whi = pack2(wv.z, wv.w);
            if (k == 0) {
                a0[2*q]   = mul2(k0, wlo);
                a0[2*q+1] = mul2(k0, whi);
                a1[2*q]   = mul2(k1, wlo);
                a1[2*q+1] = mul2(k1, whi);
            } else {
                fma2(a0[2*q],   k0, wlo);
                fma2(a0[2*q+1], k0, whi);
                fma2(a1[2*q],   k1, wlo);
                fma2(a1[2*q+1], k1, whi);
            }
        }
    }
    #pragma unroll
    for (int q = 0; q < 14; ++q) {
        unpack2(a0[q], c0[2*q], c0[2*q+1]);
        unpack2(a1[q], c1[2*q], c1[2*q+1]);
    }
}

__device__ __forceinline__ void store2(float* tile, int r0, int r1,
                                       const float c0[MD], const float c1[MD]) {
    float4* p0 = (float4*)(tile + r0 * MD);
    float4* p1 = (float4*)(tile + r1 * MD);
    #pragma unroll
    for (int q = 0; q < 7; ++q) {
        p0[q] = make_float4(c0[4*q], c0[4*q+1], c0[4*q+2], c0[4*q+3]);
        p1[q] = make_float4(c1[4*q], c1[4*q+1], c1[4*q+2], c1[4*q+3]);
    }
}

__device__ __forceinline__ void load_rows(float c0[MD], float c1[MD],
                                          const float4* __restrict__ m,
                                          int r0, int r1) {
    #pragma unroll
    for (int q = 0; q < 7; ++q) {
        float4 v0 = m[r0 * 7 + q];
        float4 v1 = m[r1 * 7 + q];
        c0[4*q] = v0.x; c0[4*q+1] = v0.y; c0[4*q+2] = v0.z; c0[4*q+3] = v0.w;
        c1[4*q] = v1.x; c1[4*q+1] = v1.y; c1[4*q+2] = v1.z; c1[4*q+3] = v1.w;
    }
}

__global__ void w2m_zero(void) { g_cnt[threadIdx.x] = 0; }

// 444 blocks x 3 warps. Warp gw = blk*3+w handles segments 2gw (low half) and
// 2gw+1 (high half); segment s = piece (s%5) of batch (s/5), 26 steps (identity
// padded). Publishes partials to g_q; 5th arriver per batch folds the product.
__global__ void __launch_bounds__(NWB * 32, 3)
w2m_main(const int* __restrict__ sent, const float* __restrict__ tab,
         float* __restrict__ out)
{
    extern __shared__ char smem_raw[];
    __shared__ __align__(8) unsigned long long mbar[NWB][2];

    int w    = (int)(threadIdx.x >> 5);
    int lane = (int)(threadIdx.x & 31);
    int gw   = blockIdx.x * NWB + w;
    if (2 * gw >= NSEG) return;           // 52 idle warps (no block syncs exist)

    int h    = lane >> 4;
    int sl   = lane & 15;
    int act  = (sl < 14);
    int r0   = act ? sl : 0;
    int r1   = act ? sl + 14 : 0;

    int segA = 2 * gw, segB = 2 * gw + 1;
    int bA = segA / NPC, pA = segA % NPC;
    int bB = segB / NPC, pB = segB % NPC;

    char* wbase = smem_raw + (size_t)w * W_STRIDE;
    float4* bufA0 = (float4*)(wbase);
    float4* bufA1 = (float4*)(wbase + MAT_BYTES);
    float4* bufB0 = (float4*)(wbase + 2 * MAT_BYTES + 16);
    float4* bufB1 = (float4*)(wbase + 3 * MAT_BYTES + 16);

    if (lane == 0) {
        mbar_init(&mbar[w][0]);
        mbar_init(&mbar[w][1]);
        fence_proxy_async_cta();
    }
    __syncwarp();

    // lane la holds step-la word index of each half's segment (identity pad = 0)
    int la = (lane < PLEN) ? lane : 0;
    int gA = pA * PLEN + la;
    int gB = pB * PLEN + la;
    int iA = (gA < SEQ) ? sent[bA * SEQ + gA] : 0;
    int iB = (gB < SEQ) ? sent[bB * SEQ + gB] : 0;

    // TMA step-1 matrices into stage 1
    {
        int a1i = __shfl_sync(0xffffffffu, iA, 1);
        int b1i = __shfl_sync(0xffffffffu, iB, 1);
        if (lane == 0) {
            mbar_expect_tx(&mbar[w][1], 2 * MAT_BYTES);
            bulk_cp(bufA1, tab + (size_t)a1i * D, MAT_BYTES, &mbar[w][1]);
            bulk_cp(bufB1, tab + (size_t)b1i * D, MAT_BYTES, &mbar[w][1]);
        }
    }

    // c = rows of step-0 matrix of this half's segment
    float c0[MD], c1[MD];
    {
        int a0i = __shfl_sync(0xffffffffu, iA, 0);
        int b0i = __shfl_sync(0xffffffffu, iB, 0);
        int i0  = h ? b0i : a0i;
        load_rows(c0, c1, (const float4*)(tab + (size_t)i0 * D), r0, r1);
    }

    unsigned ph0 = 0, ph1 = 0;

    #pragma unroll 1
    for (int s = 1; s < PLEN; ++s) {
        if (s + 1 < PLEN) {
            int an = __shfl_sync(0xffffffffu, iA, s + 1);
            int bn = __shfl_sync(0xffffffffu, iB, s + 1);
            if (lane == 0) {
                int st = (s + 1) & 1;
                void* mb = &mbar[w][st];
                mbar_expect_tx(mb, 2 * MAT_BYTES);
                bulk_cp(st ? bufA1 : bufA0, tab + (size_t)an * D, MAT_BYTES, mb);
                bulk_cp(st ? bufB1 : bufB0, tab + (size_t)bn * D, MAT_BYTES, mb);
            }
        }
        if (s & 1) { mbar_wait(&mbar[w][1], ph1); ph1 ^= 1u; }
        else       { mbar_wait(&mbar[w][0], ph0); ph0 ^= 1u; }
        const float4* wp = (s & 1) ? (h ? bufB1 : bufA1) : (h ? bufB0 : bufA0);
        mm_step2(c0, c1, wp);
    }

    // publish partials: low half -> segA, high half -> segB
    if (act) {
        float* dst = g_q + (size_t)(h ? segB : segA) * D;
        store2(dst, r0, r1, c0, c1);
    }
    __threadfence();                          // release partials
    __syncwarp();

    int oA = 0, oB = 0;
    if (lane == 0) {
        oA = atomicAdd(&g_cnt[bA], 1);
        oB = atomicAdd(&g_cnt[bB], 1);
    }
    oA = __shfl_sync(0xffffffffu, oA, 0);
    oB = __shfl_sync(0xffffffffu, oB, 0);

    #pragma unroll 1
    for (int f = 0; f < 2; ++f) {
        int fire = (f == 0) ? (oA == NPC - 1) : (oB == NPC - 1);
        if (!fire) continue;
        int b = (f == 0) ? bA : bB;

        __threadfence();                      // acquire all 5 partials
        // gather Q1..Q4 into the 4 free stage buffers via one TMA group
        if (lane == 0) {
            mbar_expect_tx(&mbar[w][0], 4 * MAT_BYTES);
            bulk_cp(bufA0, g_q + (size_t)(b * NPC + 1) * D, MAT_BYTES, &mbar[w][0]);
            bulk_cp(bufA1, g_q + (size_t)(b * NPC + 2) * D, MAT_BYTES, &mbar[w][0]);
            bulk_cp(bufB0, g_q + (size_t)(b * NPC + 3) * D, MAT_BYTES, &mbar[w][0]);
            bulk_cp(bufB1, g_q + (size_t)(b * NPC + 4) * D, MAT_BYTES, &mbar[w][0]);
        }
        // c = rows of Q0 (all lanes; both halves compute identically)
        load_rows(c0, c1, (const float4*)(g_q + (size_t)(b * NPC) * D), r0, r1);
        mbar_wait(&mbar[w][0], ph0); ph0 ^= 1u;
        mm_step2(c0, c1, bufA0);
        mm_step2(c0, c1, bufA1);
        mm_step2(c0, c1, bufB0);
        mm_step2(c0, c1, bufB1);
        if (h == 0 && act)
            store2(out + (size_t)b * D, r0, r1, c0, c1);
    }
}

extern "C" void kernel_launch(void* const* d_in, const int* in_sizes, int n_in,
                              void* d_out, int out_size)
{
    const int*   sent;
    const float* tab;
    if (in_sizes[0] < in_sizes[1]) {
        sent = (const int*)d_in[0];
        tab  = (const float*)d_in[1];
    } else {
        sent = (const int*)d_in[1];
        tab  = (const float*)d_in[0];
    }

    static int smem_set = 0;
    if (!smem_set) {
        cudaFuncSetAttribute(w2m_main,
                             cudaFuncAttributeMaxDynamicSharedMemorySize, SMEM_BYTES);
        smem_set = 1;
    }

    w2m_zero<<<1, NB>>>();
    w2m_main<<<NBLK, NWB * 32, SMEM_BYTES>>>(sent, tab, (float*)d_out);
}

// round 17
// speedup vs baseline: 1.0003x; 1.0003x over previous
#include <cuda_runtime.h>
#include <cstdint>
#include <cstddef>

#define MD   28
#define D    784
#define SEQ  128
#define NB   512
#define NWB  3             // warps per block
#define NBLK 592           // 4 blocks per SM exactly (148*4)
#define TPB  8             // tasks per batch; task = 2 pieces of 8 steps
#define PL   8             // steps per piece (16 pieces * 8 = 128, no padding)
#define NTASK (NB * TPB)   // 4096
#define MAT_BYTES 3136
#define W_STRIDE  (4 * MAT_BYTES + 16)
#define SMEM_BYTES (NWB * W_STRIDE)      // 37680 B < 48K, no opt-in needed

__device__ __align__(16) float g_q[(size_t)NB * TPB * D];  // task partials
__device__ int g_cnt[NB];                                  // fan-in counters
__device__ int g_task;                                     // work queue head

// ---------- packed f32x2 helpers ----------
__device__ __forceinline__ unsigned long long pack2(float lo, float hi) {
    unsigned long long r;
    asm("mov.b64 %0, {%1, %2};" : "=l"(r) : "f"(lo), "f"(hi));
    return r;
}
__device__ __forceinline__ void unpack2(unsigned long long v, float& lo, float& hi) {
    asm("mov.b64 {%0, %1}, %2;" : "=f"(lo), "=f"(hi) : "l"(v));
}
__device__ __forceinline__ unsigned long long mul2(unsigned long long a, unsigned long long b) {
    unsigned long long r;
    asm("mul.rn.f32x2 %0, %1, %2;" : "=l"(r) : "l"(a), "l"(b));
    return r;
}
__device__ __forceinline__ void fma2(unsigned long long& d, unsigned long long a, unsigned long long b) {
    asm("fma.rn.f32x2 %0, %1, %2, %0;" : "+l"(d) : "l"(a), "l"(b));
}

// ---------- TMA bulk-copy + mbarrier helpers ----------
__device__ __forceinline__ unsigned s2u(const void* p) {
    return (unsigned)__cvta_generic_to_shared(p);
}
__device__ __forceinline__ void mbar_init(void* mbar) {
    asm volatile("mbarrier.init.shared.b64 [%0], %1;"
                 :: "r"(s2u(mbar)), "r"(1u) : "memory");
}
__device__ __forceinline__ void mbar_expect_tx(void* mbar, unsigned bytes) {
    asm volatile("mbarrier.arrive.expect_tx.shared.b64 _, [%0], %1;"
                 :: "r"(s2u(mbar)), "r"(bytes) : "memory");
}
__device__ __forceinline__ void mbar_wait(void* mbar, unsigned parity) {
    asm volatile(
        "{\n\t"
        ".reg .pred P;\n"
        "W%=:\n\t"
        "mbarrier.try_wait.parity.acquire.cta.shared::cta.b64 P, [%0], %1, 0x989680;\n\t"
        "@P bra D%=;\n\t"
        "bra W%=;\n"
        "D%=:\n\t"
        "}"
        :: "r"(s2u(mbar)), "r"(parity) : "memory");
}
__device__ __forceinline__ void bulk_cp(void* dst_smem, const void* src_gmem,
                                        unsigned bytes, void* mbar) {
    asm volatile(
        "cp.async.bulk.shared::cta.global.mbarrier::complete_tx::bytes [%0], [%1], %2, [%3];"
        :: "r"(s2u(dst_smem)), "l"(src_gmem), "r"(bytes), "r"(s2u(mbar)) : "memory");
}
__device__ __forceinline__ void fence_proxy_async_cta() {
    asm volatile("fence.proxy.async.shared::cta;" ::: "memory");
}

// Two rows per lane: {c0,c1} = rows sl, sl+14. W in smem; the two 16-lane
// halves may pass different pointers (dual broadcast).
__device__ __forceinline__ void mm_step2(float c0[MD], float c1[MD],
                                         const float4* __restrict__ w) {
    unsigned long long a0[14], a1[14];
    #pragma unroll
    for (int k = 0; k < MD; ++k) {
        unsigned long long k0 = pack2(c0[k], c0[k]);
        unsigned long long k1 = pack2(c1[k], c1[k]);
        #pragma unroll
        for (int q = 0; q < 7; ++q) {
            float4 wv = w[k * 7 + q];
            unsigned long long wlo = pack2(wv.x, wv.y);
            unsigned long long whi = pack2(wv.z, wv.w);
            if (k == 0) {
                a0[2*q]   = mul2(k0, wlo);
                a0[2*q+1] = mul2(k0, whi);
                a1[2*q]   = mul2(k1, wlo);
                a1[2*q+1] = mul2(k1, whi);
            } else {
                fma2(a0[2*q],   k0, wlo);
                fma2(a0[2*q+1], k0, whi);
                fma2(a1[2*q],   k1, wlo);
                fma2(a1[2*q+1], k1, whi);
            }
        }
    }
    #pragma unroll
    for (int q = 0; q < 14; ++q) {
        unpack2(a0[q], c0[2*q], c0[2*q+1]);
        unpack2(a1[q], c1[2*q], c1[2*q+1]);
    }
}

__device__ __forceinline__ void store2(float* tile, int r0, int r1,
                                       const float c0[MD], const float c1[MD]) {
    float4* p0 = (float4*)(tile + r0 * MD);
    float4* p1 = (float4*)(tile + r1 * MD);
    #pragma unroll
    for (int q = 0; q < 7; ++q) {
        p0[q] = make_float4(c0[4*q], c0[4*q+1], c0[4*q+2], c0[4*q+3]);
        p1[q] = make_float4(c1[4*q], c1[4*q+1], c1[4*q+2], c1[4*q+3]);
    }
}

__device__ __forceinline__ void load_rows(float c0[MD], float c1[MD],
                                          const float4* __restrict__ m,
                                          int r0, int r1) {
    #pragma unroll
    for (int q = 0; q < 7; ++q) {
        float4 v0 = m[r0 * 7 + q];
        float4 v1 = m[r1 * 7 + q];
        c0[4*q] = v0.x; c0[4*q+1] = v0.y; c0[4*q+2] = v0.z; c0[4*q+3] = v0.w;
        c1[4*q] = v1.x; c1[4*q+1] = v1.y; c1[4*q+2] = v1.z; c1[4*q+3] = v1.w;
    }
}

__global__ void w2m_zero(void) {
    g_cnt[threadIdx.x] = 0;
    if (threadIdx.x == 0) g_task = 0;
}

// Persistent: 592 blocks x 3 warps. Each warp loops pulling tasks from g_task.
// Task k: batch b=k/8, slot t=k%8; chains [16t,16t+8) and [16t+8,16t+16),
// Q = PA*PB published to g_q[b*8+t]; 8th arriver folds out = Q0*...*Q7.
__global__ void __launch_bounds__(NWB * 32, 4)
w2m_main(const int* __restrict__ sent, const float* __restrict__ tab,
         float* __restrict__ out)
{
    extern __shared__ char smem_raw[];
    __shared__ __align__(8) unsigned long long mbar[NWB][2];

    int w    = (int)(threadIdx.x >> 5);
    int lane = (int)(threadIdx.x & 31);
    int h    = lane >> 4;
    int sl   = lane & 15;
    int act  = (sl < 14);
    int r0   = act ? sl : 0;
    int r1   = act ? sl + 14 : 0;

    char* wbase = smem_raw + (size_t)w * W_STRIDE;
    float4* bufA0 = (float4*)(wbase);
    float4* bufA1 = (float4*)(wbase + MAT_BYTES);
    float4* bufB0 = (float4*)(wbase + 2 * MAT_BYTES + 16);
    float4* bufB1 = (float4*)(wbase + 3 * MAT_BYTES + 16);

    if (lane == 0) {
        mbar_init(&mbar[w][0]);
        mbar_init(&mbar[w][1]);
        fence_proxy_async_cta();
    }
    __syncwarp();

    unsigned ph0 = 0, ph1 = 0;      // mbarrier phase parity, persists across tasks
    float c0[MD], c1[MD];

    #pragma unroll 1
    for (;;) {
        int k = 0;
        if (lane == 0) k = atomicAdd(&g_task, 1);
        k = __shfl_sync(0xffffffffu, k, 0);
        if (k >= NTASK) break;

        int b = k >> 3, t = k & 7;
        int base = b * SEQ + t * 16;
        int la = lane & 7;
        int iA = sent[base + la];          // step la of chain A (lanes replicated)
        int iB = sent[base + 8 + la];

        // first TMA: step-1 matrices of both chains into stage 1
        {
            int a1i = __shfl_sync(0xffffffffu, iA, 1);
            int b1i = __shfl_sync(0xffffffffu, iB, 1);
            if (lane == 0) {
                mbar_expect_tx(&mbar[w][1], 2 * MAT_BYTES);
                bulk_cp(bufA1, tab + (size_t)a1i * D, MAT_BYTES, &mbar[w][1]);
                bulk_cp(bufB1, tab + (size_t)b1i * D, MAT_BYTES, &mbar[w][1]);
            }
        }

        // c = rows of step-0 matrix of this half's chain
        {
            int a0i = __shfl_sync(0xffffffffu, iA, 0);
            int b0i = __shfl_sync(0xffffffffu, iB, 0);
            int i0  = h ? b0i : a0i;
            load_rows(c0, c1, (const float4*)(tab + (size_t)i0 * D), r0, r1);
        }

        #pragma unroll 1
        for (int s = 1; s < PL; ++s) {
            if (s + 1 < PL) {
                int an = __shfl_sync(0xffffffffu, iA, s + 1);
                int bn = __shfl_sync(0xffffffffu, iB, s + 1);
                if (lane == 0) {
                    int st = (s + 1) & 1;
                    void* mb = &mbar[w][st];
                    mbar_expect_tx(mb, 2 * MAT_BYTES);
                    bulk_cp(st ? bufA1 : bufA0, tab + (size_t)an * D, MAT_BYTES, mb);
                    bulk_cp(st ? bufB1 : bufB0, tab + (size_t)bn * D, MAT_BYTES, mb);
                }
            }
            if (s & 1) { mbar_wait(&mbar[w][1], ph1); ph1 ^= 1u; }
            else       { mbar_wait(&mbar[w][0], ph0); ph0 ^= 1u; }
            const float4* wp = (s & 1) ? (h ? bufB1 : bufA1) : (h ? bufB0 : bufA0);
            mm_step2(c0, c1, wp);
        }

        // join: Q = PA * PB  (all stage TMAs drained; bufB0 free for PB)
        if (h == 1 && act) store2((float*)bufB0, r0, r1, c0, c1);
        __syncwarp();
        mm_step2(c0, c1, bufB0);

        // publish Q and fan-in
        if (h == 0 && act)
            store2(g_q + (size_t)k * D, r0, r1, c0, c1);
        __threadfence();
        __syncwarp();

        int old = 0;
        if (lane == 0) old = atomicAdd(&g_cnt[b], 1);
        old = __shfl_sync(0xffffffffu, old, 0);
        if (old != TPB - 1) continue;

        // ---- finisher: out = Q0 * Q1 * ... * Q7 ----
        __threadfence();
        const float* qb = g_q + (size_t)b * TPB * D;
        if (lane == 0) {
            mbar_expect_tx(&mbar[w][0], 4 * MAT_BYTES);
            bulk_cp(bufA0, qb + 1 * D, MAT_BYTES, &mbar[w][0]);
            bulk_cp(bufA1, qb + 2 * D, MAT_BYTES, &mbar[w][0]);
            bulk_cp(bufB0, qb + 3 * D, MAT_BYTES, &mbar[w][0]);
            bulk_cp(bufB1, qb + 4 * D, MAT_BYTES, &mbar[w][0]);
        }
        load_rows(c0, c1, (const float4*)qb, r0, r1);      // Q0 rows
        mbar_wait(&mbar[w][0], ph0); ph0 ^= 1u;
        mm_step2(c0, c1, bufA0);
        mm_step2(c0, c1, bufA1);
        mm_step2(c0, c1, bufB0);
        mm_step2(c0, c1, bufB1);
        if (lane == 0) {
            mbar_expect_tx(&mbar[w][0], 3 * MAT_BYTES);
            bulk_cp(bufA0, qb + 5 * D, MAT_BYTES, &mbar[w][0]);
            bulk_cp(bufA1, qb + 6 * D, MAT_BYTES, &mbar[w][0]);
            bulk_cp(bufB0, qb + 7 * D, MAT_BYTES, &mbar[w][0]);
        }
        mbar_wait(&mbar[w][0], ph0); ph0 ^= 1u;
        mm_step2(c0, c1, bufA0);
        mm_step2(c0, c1, bufA1);
        mm_step2(c0, c1, bufB0);
        if (h == 0 && act)
            store2(out + (size_t)b * D, r0, r1, c0, c1);
    }
}

extern "C" void kernel_launch(void* const* d_in, const int* in_sizes, int n_in,
                              void* d_out, int out_size)
{
    const int*   sent;
    const float* tab;
    if (in_sizes[0] < in_sizes[1]) {
        sent = (const int*)d_in[0];
        tab  = (const float*)d_in[1];
    } else {
        sent = (const int*)d_in[1];
        tab  = (const float*)d_in[0];
    }

    w2m_zero<<<1, NB>>>();
    w2m_main<<<NBLK, NWB * 32, SMEM_BYTES>>>(sent, tab, (float*)d_out);
}